// round 16
// baseline (speedup 1.0000x reference)
#include <cuda_runtime.h>
#include <stdint.h>

// HistLayer: 128-bin histogram over 8x3x256x256 fp32 in [0,1).
// (Byte-identical resubmission of R15 — previous attempt failed with
//  "device busy or unavailable" at harness init; kernel never ran.)
//
// Count-based reformulation (validated R6..R14, rel_err ~5e-7):
//   f = 128*x exact; ad = |f - rint(f)|; include <=> ad > CUT;
//   out = count * SCALE, SCALE = (1 + K1*E[ad|inc]) / 65536.
// R15: single-kernel finalize; the per-thread __threadfence (measured
// +1.3us fusion tax in R14) replaced by decoupled-lookback ordering:
// relaxed scratch atomics -> __syncthreads -> ONE atom.acq_rel.gpu
// counter increment per block.

#define NTHREADS 128
#define NBINS 128
#define PLANES 24
#define V4_PER_PLANE 16384
#define BLOCKS_PER_PLANE 64
#define NBLOCKS (PLANES * BLOCKS_PER_PLANE)    // 1536
#define V4_PER_BLOCK 256                        // 1024 px, 2 float4/thread
#define HWORDS (NBINS / 2 * 32)                 // 2048 words = 8 KB
#define U4_PER_THREAD (HWORDS / 4 / NTHREADS)   // 4 uint4/thread to zero

#define CUT 7.6673e-4f                          // 128 * 2^-24 / ln(1.01f)
#define SCALE 1.5259086e-5f                     // (1 + 1.94648e-5) / 65536

// Zero-initialized at module load; every launch returns them to zero.
__device__ unsigned int g_scratch[PLANES * NBINS];
__device__ unsigned int g_count[PLANES];

__device__ __forceinline__ void pixel_inc_addr(float x, int base, int& addr, int& inc) {
    float f = x * 128.0f;        // exact
    float r = rintf(f);
    float ad = fabsf(f - r);     // exact
    int b = (int)f;              // trunc, f in [0,128)
    int c = (ad > CUT) ? 1 : 0;
    inc  = c << ((b & 1) << 2);              // count into lo/hi nibble
    addr = (b >> 1) * 128 + base;
}

// Pair RMW: merge on BYTE-ADDRESS equality (covers same-bin and the
// adjacent-bin-sharing-a-byte case). Equal addrs -> identical totals ->
// duplicate stores idempotent; nibble sums never carry (each nibble <= 8).
// Across pairs, per-thread same-address LSU program order keeps RMWs correct.
__device__ __forceinline__ void rmw_pair(unsigned char* __restrict__ hb,
                                         int i0, int inc0, int i1, int inc1) {
    bool eq = (i0 == i1);
    int t0 = inc0 + (eq ? inc1 : 0);
    int t1 = inc1 + (eq ? inc0 : 0);
    unsigned char a0 = hb[i0];
    unsigned char a1 = hb[i1];
    hb[i0] = (unsigned char)(a0 + t0);
    hb[i1] = (unsigned char)(a1 + t1);
}

__global__ __launch_bounds__(NTHREADS, 12)
void hist_kernel(const float* __restrict__ in, float* __restrict__ out) {
    __shared__ uint32_t hw[HWORDS];              // 8 KB nibble histograms
    __shared__ unsigned int s_last;
    unsigned char* hb = reinterpret_cast<unsigned char*>(hw);

    const int tid  = threadIdx.x;
    const int lane = tid & 31;
    const int base = lane * 4 + (tid >> 5);      // byte owner slot

    const int plane = blockIdx.x / BLOCKS_PER_PLANE;
    const int sub   = blockIdx.x % BLOCKS_PER_PLANE;
    const float4* __restrict__ src =
        reinterpret_cast<const float4*>(in) +
        (size_t)plane * V4_PER_PLANE + sub * V4_PER_BLOCK;

    // Issue global loads first; DRAM wait hides behind smem zero + barrier.
    float4 v0 = src[tid];
    float4 v1 = src[tid + NTHREADS];

    // Zero ALL 8 KB (4 uint4 per thread).
    uint4* h4 = reinterpret_cast<uint4*>(hw);
    #pragma unroll
    for (int k = 0; k < U4_PER_THREAD; k++)
        h4[tid + k * NTHREADS] = make_uint4(0u, 0u, 0u, 0u);
    __syncthreads();

    // Flat ILP block of all 8 (addr,inc), then 4 back-to-back RMW pairs.
    int i0, i1, i2, i3, i4, i5, i6, i7;
    int n0, n1, n2, n3, n4, n5, n6, n7;
    pixel_inc_addr(v0.x, base, i0, n0);
    pixel_inc_addr(v0.y, base, i1, n1);
    pixel_inc_addr(v0.z, base, i2, n2);
    pixel_inc_addr(v0.w, base, i3, n3);
    pixel_inc_addr(v1.x, base, i4, n4);
    pixel_inc_addr(v1.y, base, i5, n5);
    pixel_inc_addr(v1.z, base, i6, n6);
    pixel_inc_addr(v1.w, base, i7, n7);

    rmw_pair(hb, i0, n0, i1, n1);
    rmw_pair(hb, i2, n2, i3, n3);
    rmw_pair(hb, i4, n4, i5, n5);
    rmw_pair(hb, i6, n6, i7, n7);
    __syncthreads();

    // Reduce (R13): raw dp4a gives T = S_lo + 16*S_hi; masked dp4a gives S_hi;
    // S_lo = T - 16*S_hi. Threads 2r, 2r+1 split row r; shfl_xor merges halves.
    int total;
    {
        const int r    = tid >> 1;
        const int half = tid & 1;
        const uint4* row4 = reinterpret_cast<const uint4*>(&hw[r << 5]);
        int t_a = 0, t_b = 0, h_a = 0, h_b = 0;
        #pragma unroll
        for (int j = 0; j < 4; j++) {
            uint4 u = row4[half * 4 + ((j + r) & 3)];
            t_a = __dp4a((int)u.x, 0x01010101, t_a);
            h_a = __dp4a((int)((u.x >> 4) & 0x0F0F0F0Fu), 0x01010101, h_a);
            t_b = __dp4a((int)u.y, 0x01010101, t_b);
            h_b = __dp4a((int)((u.y >> 4) & 0x0F0F0F0Fu), 0x01010101, h_b);
            t_a = __dp4a((int)u.z, 0x01010101, t_a);
            h_a = __dp4a((int)((u.z >> 4) & 0x0F0F0F0Fu), 0x01010101, h_a);
            t_b = __dp4a((int)u.w, 0x01010101, t_b);
            h_b = __dp4a((int)((u.w >> 4) & 0x0F0F0F0Fu), 0x01010101, h_b);
        }
        int t_sum  = t_a + t_b;              // S_lo + 16*S_hi (exact)
        int acc_hi = h_a + h_b;              // S_hi
        int acc_lo = t_sum - (acc_hi << 4);  // S_lo
        int send = half ? acc_lo : acc_hi;
        int recv = __shfl_xor_sync(0xFFFFFFFFu, send, 1);
        total = (half ? acc_hi : acc_lo) + recv;   // bin = 2r + half = tid
    }

    // Relaxed integer atomic partial (order-independent -> bit-deterministic).
    atomicAdd(&g_scratch[plane * NBINS + tid], (unsigned int)total);

    // Decoupled-lookback ordering (replaces per-thread __threadfence):
    // syncthreads puts every thread's scratch atomic happens-before thread 0's
    // RELEASE counter increment; the last block's ACQUIRE (same atom) +
    // syncthreads makes all 64 blocks' partials visible to its reads.
    __syncthreads();
    if (tid == 0) {
        unsigned int old;
        asm volatile("atom.acq_rel.gpu.global.add.u32 %0, [%1], %2;"
                     : "=r"(old) : "l"(&g_count[plane]), "r"(1u) : "memory");
        s_last = old;
    }
    __syncthreads();
    if (s_last == BLOCKS_PER_PLANE - 1) {
        unsigned int s = __ldcg(&g_scratch[plane * NBINS + tid]);
        out[plane * NBINS + tid] = (float)s * SCALE;   // overwrites poison
        g_scratch[plane * NBINS + tid] = 0u;           // reset for replay
        if (tid == 0) g_count[plane] = 0u;
    }
}

extern "C" void kernel_launch(void* const* d_in, const int* in_sizes, int n_in,
                              void* d_out, int out_size) {
    const float* in = (const float*)d_in[0];
    float* out = (float*)d_out;
    hist_kernel<<<NBLOCKS, NTHREADS>>>(in, out);   // single graph node
}

// round 17
// speedup vs baseline: 1.0898x; 1.0898x over previous
#include <cuda_runtime.h>
#include <stdint.h>

// HistLayer: 128-bin histogram over 8x3x256x256 fp32 in [0,1).
// Count-based reformulation (validated R6..R16, rel_err ~5e-7):
//   f = 128*x exact; ad = |f - rint(f)|; include <=> ad > CUT;
//   out = count * SCALE, SCALE = (1 + K1*E[ad|inc]) / 65536.
// R17: two kernels, but the finalize kernel is launched with
// PROGRAMMATIC DEPENDENT LAUNCH so its launch latency overlaps the hist
// kernel's execution. Hist kernel = champion R13 mainloop + fire-and-forget
// RED.ADD to integer scratch (NO fence/counter/epilogue convoy — the
// measured +1.3..2.0us fusion tax of R14/R16). Finalize kernel gridsyncs,
// writes out (overwriting harness poison), and RE-ZEROS scratch so every
// launch starts from identical state (graph-replay determinism).

#define NTHREADS 128
#define NBINS 128
#define PLANES 24
#define V4_PER_PLANE 16384
#define BLOCKS_PER_PLANE 64
#define NBLOCKS (PLANES * BLOCKS_PER_PLANE)    // 1536
#define V4_PER_BLOCK 256                        // 1024 px, 2 float4/thread
#define HWORDS (NBINS / 2 * 32)                 // 2048 words = 8 KB
#define U4_PER_THREAD (HWORDS / 4 / NTHREADS)   // 4 uint4/thread to zero

#define CUT 7.6673e-4f                          // 128 * 2^-24 / ln(1.01f)
#define SCALE 1.5259086e-5f                     // (1 + 1.94648e-5) / 65536

// Zero-initialized at module load; finalize kernel returns it to zero.
__device__ unsigned int g_scratch[PLANES * NBINS];

__device__ __forceinline__ void pixel_inc_addr(float x, int base, int& addr, int& inc) {
    float f = x * 128.0f;        // exact
    float r = rintf(f);
    float ad = fabsf(f - r);     // exact
    int b = (int)f;              // trunc, f in [0,128)
    int c = (ad > CUT) ? 1 : 0;
    inc  = c << ((b & 1) << 2);              // count into lo/hi nibble
    addr = (b >> 1) * 128 + base;
}

// Pair RMW: merge on BYTE-ADDRESS equality (covers same-bin and the
// adjacent-bin-sharing-a-byte case). Equal addrs -> identical totals ->
// duplicate stores idempotent; nibble sums never carry (each nibble <= 8).
// Across pairs, per-thread same-address LSU program order keeps RMWs correct.
__device__ __forceinline__ void rmw_pair(unsigned char* __restrict__ hb,
                                         int i0, int inc0, int i1, int inc1) {
    bool eq = (i0 == i1);
    int t0 = inc0 + (eq ? inc1 : 0);
    int t1 = inc1 + (eq ? inc0 : 0);
    unsigned char a0 = hb[i0];
    unsigned char a1 = hb[i1];
    hb[i0] = (unsigned char)(a0 + t0);
    hb[i1] = (unsigned char)(a1 + t1);
}

__global__ __launch_bounds__(NTHREADS, 12)
void hist_kernel(const float* __restrict__ in) {
    __shared__ uint32_t hw[HWORDS];              // 8 KB nibble histograms
    unsigned char* hb = reinterpret_cast<unsigned char*>(hw);

    const int tid  = threadIdx.x;
    const int lane = tid & 31;
    const int base = lane * 4 + (tid >> 5);      // byte owner slot

    const int plane = blockIdx.x / BLOCKS_PER_PLANE;
    const int sub   = blockIdx.x % BLOCKS_PER_PLANE;
    const float4* __restrict__ src =
        reinterpret_cast<const float4*>(in) +
        (size_t)plane * V4_PER_PLANE + sub * V4_PER_BLOCK;

    // Issue global loads first; DRAM wait hides behind smem zero + barrier.
    float4 v0 = src[tid];
    float4 v1 = src[tid + NTHREADS];

    // Zero ALL 8 KB (4 uint4 per thread).
    uint4* h4 = reinterpret_cast<uint4*>(hw);
    #pragma unroll
    for (int k = 0; k < U4_PER_THREAD; k++)
        h4[tid + k * NTHREADS] = make_uint4(0u, 0u, 0u, 0u);
    __syncthreads();

    // Flat ILP block of all 8 (addr,inc), then 4 back-to-back RMW pairs.
    int i0, i1, i2, i3, i4, i5, i6, i7;
    int n0, n1, n2, n3, n4, n5, n6, n7;
    pixel_inc_addr(v0.x, base, i0, n0);
    pixel_inc_addr(v0.y, base, i1, n1);
    pixel_inc_addr(v0.z, base, i2, n2);
    pixel_inc_addr(v0.w, base, i3, n3);
    pixel_inc_addr(v1.x, base, i4, n4);
    pixel_inc_addr(v1.y, base, i5, n5);
    pixel_inc_addr(v1.z, base, i6, n6);
    pixel_inc_addr(v1.w, base, i7, n7);

    rmw_pair(hb, i0, n0, i1, n1);
    rmw_pair(hb, i2, n2, i3, n3);
    rmw_pair(hb, i4, n4, i5, n5);
    rmw_pair(hb, i6, n6, i7, n7);
    __syncthreads();

    // Reduce (R13): raw dp4a gives T = S_lo + 16*S_hi; masked dp4a gives S_hi;
    // S_lo = T - 16*S_hi. Threads 2r, 2r+1 split row r; shfl_xor merges halves.
    int total;
    {
        const int r    = tid >> 1;
        const int half = tid & 1;
        const uint4* row4 = reinterpret_cast<const uint4*>(&hw[r << 5]);
        int t_a = 0, t_b = 0, h_a = 0, h_b = 0;
        #pragma unroll
        for (int j = 0; j < 4; j++) {
            uint4 u = row4[half * 4 + ((j + r) & 3)];
            t_a = __dp4a((int)u.x, 0x01010101, t_a);
            h_a = __dp4a((int)((u.x >> 4) & 0x0F0F0F0Fu), 0x01010101, h_a);
            t_b = __dp4a((int)u.y, 0x01010101, t_b);
            h_b = __dp4a((int)((u.y >> 4) & 0x0F0F0F0Fu), 0x01010101, h_b);
            t_a = __dp4a((int)u.z, 0x01010101, t_a);
            h_a = __dp4a((int)((u.z >> 4) & 0x0F0F0F0Fu), 0x01010101, h_a);
            t_b = __dp4a((int)u.w, 0x01010101, t_b);
            h_b = __dp4a((int)((u.w >> 4) & 0x0F0F0F0Fu), 0x01010101, h_b);
        }
        int t_sum  = t_a + t_b;              // S_lo + 16*S_hi (exact)
        int acc_hi = h_a + h_b;              // S_hi
        int acc_lo = t_sum - (acc_hi << 4);  // S_lo
        int send = half ? acc_lo : acc_hi;
        int recv = __shfl_xor_sync(0xFFFFFFFFu, send, 1);
        total = (half ? acc_hi : acc_lo) + recv;   // bin = 2r + half = tid
    }

    // Fire-and-forget integer RED (return unused -> REDG, no wait, no fence).
    atomicAdd(&g_scratch[plane * NBINS + tid], (unsigned int)total);
    // Implicit programmatic-launch trigger fires at kernel exit.
}

__global__ __launch_bounds__(NTHREADS, 1)
void finalize_kernel(float* __restrict__ out) {
    // PDL: we may start while hist_kernel is still running; this blocks until
    // hist_kernel completes and makes its memory (incl. REDG in L2) visible.
    cudaGridDependencySynchronize();

    const int idx = blockIdx.x * NTHREADS + threadIdx.x;   // 24*128 = 3072
    unsigned int s = __ldcg(&g_scratch[idx]);
    out[idx] = (float)s * SCALE;       // overwrites harness poison
    g_scratch[idx] = 0u;               // reset for graph replay determinism
}

extern "C" void kernel_launch(void* const* d_in, const int* in_sizes, int n_in,
                              void* d_out, int out_size) {
    const float* in = (const float*)d_in[0];
    float* out = (float*)d_out;

    hist_kernel<<<NBLOCKS, NTHREADS>>>(in);

    // Programmatic dependent launch: finalize's launch overhead overlaps
    // hist_kernel's execution; correctness ordering comes from
    // cudaGridDependencySynchronize() inside finalize_kernel.
    cudaLaunchConfig_t cfg = {};
    cfg.gridDim  = dim3(PLANES, 1, 1);       // 24 blocks x 128 = 3072 outputs
    cfg.blockDim = dim3(NTHREADS, 1, 1);
    cudaLaunchAttribute attr[1];
    attr[0].id = cudaLaunchAttributeProgrammaticStreamSerialization;
    attr[0].val.programmaticStreamSerializationAllowed = 1;
    cfg.attrs = attr;
    cfg.numAttrs = 1;
    cudaLaunchKernelEx(&cfg, finalize_kernel, out);
}